// round 1
// baseline (speedup 1.0000x reference)
#include <cuda_runtime.h>
#include <math.h>

#define B_SZ 64
#define T_SZ 64
#define NI 2048
#define NH 2048
#define MB 4
#define MN 128
#define MW 20
#define M_ROWS (B_SZ * T_SZ)  // 4096

// Scratch (allocation-free rule: device globals)
__device__ float g_pre[(size_t)M_ROWS * NH];  // X @ W_in + b_in   [B*T, NH]
__device__ float g_H[(size_t)M_ROWS * NH];    // hidden states     [B*T, NH]

// ---------------- packed f32x2 helpers (full-rate fp32 on Blackwell) --------
__device__ __forceinline__ unsigned long long pk2(float lo, float hi) {
    unsigned long long r;
    asm("mov.b64 %0, {%1, %2};" : "=l"(r) : "f"(lo), "f"(hi));
    return r;
}
__device__ __forceinline__ unsigned long long ffma2(unsigned long long a,
                                                    unsigned long long b,
                                                    unsigned long long c) {
    unsigned long long d;
    asm("fma.rn.f32x2 %0, %1, %2, %3;" : "=l"(d) : "l"(a), "l"(b), "l"(c));
    return d;
}
__device__ __forceinline__ float2 upk2(unsigned long long v) {
    float2 f;
    asm("mov.b64 {%0, %1}, %2;" : "=f"(f.x), "=f"(f.y) : "l"(v));
    return f;
}

// ---------------- GEMM: C[M,N] = act(A[M,K] @ B[K,N] + bias[N]) -------------
// MODE 0: A = param (x), C = g_pre, no activation
// MODE 1: A = g_H,       C = param (out), clip to [0,1]
// BM=BN=128, BK=16, 256 threads, 8x8 per thread (4+4 split), f32x2 math.
template <int MODE>
__global__ __launch_bounds__(256) void gemm_k(const float* __restrict__ Ain,
                                              const float* __restrict__ Bm,
                                              const float* __restrict__ bias,
                                              float* __restrict__ Cout,
                                              int M, int N, int K) {
    __shared__ float As[16][132];  // transposed A tile, padded
    __shared__ float Bs[16][128];

    const float* __restrict__ A = (MODE == 0) ? Ain : g_H;
    float* __restrict__ C = (MODE == 0) ? g_pre : Cout;

    const int tid = threadIdx.x;
    const int bx = blockIdx.x, by = blockIdx.y;
    const int tx = tid & 15, ty = tid >> 4;

    // A tile load: each thread loads 8 consecutive floats of one row
    const int a_row = tid >> 1;
    const int a_col = (tid & 1) * 8;
    const float* Ap = A + (size_t)(by * 128 + a_row) * K + a_col;
    // B tile load: two float4 rows per thread
    const int b_row0 = tid >> 5;          // 0..7
    const int b_col0 = (tid & 31) * 4;    // 0..124
    const float* Bp0 = Bm + (size_t)b_row0 * N + bx * 128 + b_col0;
    const float* Bp1 = Bm + (size_t)(b_row0 + 8) * N + bx * 128 + b_col0;

    unsigned long long acc[8][4];
#pragma unroll
    for (int r = 0; r < 8; r++)
#pragma unroll
        for (int c = 0; c < 4; c++) acc[r][c] = pk2(0.f, 0.f);

    float4 pa0, pa1, pb0, pb1;
    pa0 = *(const float4*)(Ap);
    pa1 = *(const float4*)(Ap + 4);
    pb0 = *(const float4*)(Bp0);
    pb1 = *(const float4*)(Bp1);

    const int NT = K / 16;
    for (int kt = 0; kt < NT; kt++) {
        // commit staged tile to smem
        {
            float av[8] = {pa0.x, pa0.y, pa0.z, pa0.w, pa1.x, pa1.y, pa1.z, pa1.w};
#pragma unroll
            for (int c = 0; c < 8; c++) As[a_col + c][a_row] = av[c];
            *(float4*)&Bs[b_row0][b_col0] = pb0;
            *(float4*)&Bs[b_row0 + 8][b_col0] = pb1;
        }
        __syncthreads();
        // prefetch next tile (overlaps with compute below)
        if (kt + 1 < NT) {
            const float* Ap2 = Ap + (kt + 1) * 16;
            pa0 = *(const float4*)(Ap2);
            pa1 = *(const float4*)(Ap2 + 4);
            const float* Bq0 = Bp0 + (size_t)(kt + 1) * 16 * N;
            const float* Bq1 = Bp1 + (size_t)(kt + 1) * 16 * N;
            pb0 = *(const float4*)(Bq0);
            pb1 = *(const float4*)(Bq1);
        }
#pragma unroll
        for (int kk = 0; kk < 16; kk++) {
            float4 a0 = *(const float4*)&As[kk][ty * 4];
            float4 a1 = *(const float4*)&As[kk][64 + ty * 4];
            float4 b0 = *(const float4*)&Bs[kk][tx * 4];
            float4 b1 = *(const float4*)&Bs[kk][64 + tx * 4];
            unsigned long long bp[4];
            bp[0] = pk2(b0.x, b0.y);
            bp[1] = pk2(b0.z, b0.w);
            bp[2] = pk2(b1.x, b1.y);
            bp[3] = pk2(b1.z, b1.w);
            float av[8] = {a0.x, a0.y, a0.z, a0.w, a1.x, a1.y, a1.z, a1.w};
#pragma unroll
            for (int r = 0; r < 8; r++) {
                unsigned long long ap = pk2(av[r], av[r]);
#pragma unroll
                for (int c = 0; c < 4; c++) acc[r][c] = ffma2(ap, bp[c], acc[r][c]);
            }
        }
        __syncthreads();
    }

    // epilogue
    const float* bp_lo = bias + bx * 128 + tx * 4;
    float4 bl = *(const float4*)(bp_lo);
    float4 bh = *(const float4*)(bp_lo + 64);
#pragma unroll
    for (int r = 0; r < 8; r++) {
        int row = by * 128 + ((r < 4) ? ty * 4 + r : 64 + ty * 4 + (r - 4));
        float2 v0 = upk2(acc[r][0]);
        float2 v1 = upk2(acc[r][1]);
        float2 v2 = upk2(acc[r][2]);
        float2 v3 = upk2(acc[r][3]);
        float4 lo = {v0.x + bl.x, v0.y + bl.y, v1.x + bl.z, v1.y + bl.w};
        float4 hi = {v2.x + bh.x, v2.y + bh.y, v3.x + bh.z, v3.y + bh.w};
        if (MODE == 1) {
            lo.x = fminf(fmaxf(lo.x, 0.f), 1.f);
            lo.y = fminf(fmaxf(lo.y, 0.f), 1.f);
            lo.z = fminf(fmaxf(lo.z, 0.f), 1.f);
            lo.w = fminf(fmaxf(lo.w, 0.f), 1.f);
            hi.x = fminf(fmaxf(hi.x, 0.f), 1.f);
            hi.y = fminf(fmaxf(hi.y, 0.f), 1.f);
            hi.z = fminf(fmaxf(hi.z, 0.f), 1.f);
            hi.w = fminf(fmaxf(hi.w, 0.f), 1.f);
        }
        *(float4*)&C[(size_t)row * N + bx * 128 + tx * 4] = lo;
        *(float4*)&C[(size_t)row * N + bx * 128 + 64 + tx * 4] = hi;
    }
}

// ---------------- Recurrence: one block per batch row, all 64 steps ---------
__global__ __launch_bounds__(256) void recur_k(const float* __restrict__ h0,
                                               const float* __restrict__ W_key,
                                               const float* __restrict__ b_key,
                                               const float* __restrict__ W_read,
                                               const float* __restrict__ b_read,
                                               const float* __restrict__ memory) {
    __shared__ float sh[NH];           // current hidden state (8 KB)
    __shared__ float sbank[MN * MW];   // current bank (10 KB)
    __shared__ float sbnorm[MB * MN];  // all bank-row norms (2 KB)
    __shared__ float sprob[MN];
    __shared__ float sk[MW];
    __shared__ float sr[MW];
    __shared__ float sred[8 * MW];
    __shared__ float sknorm;

    const int b = blockIdx.x;
    const int tid = threadIdx.x;
    const int lane = tid & 31, warp = tid >> 5;

    for (int i = tid; i < NH; i += 256) sh[i] = h0[(size_t)b * NH + i];
    for (int i = tid; i < MB * MN; i += 256) {
        float s = 0.f;
        const float* row = memory + (size_t)i * MW;
#pragma unroll
        for (int m = 0; m < MW; m++) s += row[m] * row[m];
        sbnorm[i] = sqrtf(s);
    }
    __syncthreads();

    for (int t = 0; t < T_SZ; t++) {
        const int bk = t & (MB - 1);
        const float* bank = memory + (size_t)bk * MN * MW;
        for (int i = tid; i < MN * MW; i += 256) sbank[i] = bank[i];
        __syncthreads();

        // k = h @ W_key + b_key   (parallel over the K dim, 20 partials/thread)
        float part[MW];
#pragma unroll
        for (int j = 0; j < MW; j++) part[j] = 0.f;
        for (int i = tid; i < NH; i += 256) {
            float hv = sh[i];
            const float4* wr = (const float4*)(W_key + (size_t)i * MW);
#pragma unroll
            for (int q = 0; q < 5; q++) {
                float4 w = wr[q];
                part[q * 4 + 0] += hv * w.x;
                part[q * 4 + 1] += hv * w.y;
                part[q * 4 + 2] += hv * w.z;
                part[q * 4 + 3] += hv * w.w;
            }
        }
#pragma unroll
        for (int j = 0; j < MW; j++) {
#pragma unroll
            for (int o = 16; o > 0; o >>= 1)
                part[j] += __shfl_xor_sync(0xffffffffu, part[j], o);
        }
        if (lane == 0) {
#pragma unroll
            for (int j = 0; j < MW; j++) sred[warp * MW + j] = part[j];
        }
        __syncthreads();
        if (tid < MW) {
            float s = b_key[tid];
#pragma unroll
            for (int w = 0; w < 8; w++) s += sred[w * MW + tid];
            sk[tid] = s;
        }
        __syncthreads();
        if (tid == 0) {
            float s = 0.f;
#pragma unroll
            for (int j = 0; j < MW; j++) s += sk[j] * sk[j];
            sknorm = sqrtf(s);
        }
        __syncthreads();

        // cosine similarity vs bank rows
        if (tid < MN) {
            float d = 0.f;
            const float* bn = &sbank[tid * MW];
#pragma unroll
            for (int j = 0; j < MW; j++) d += sk[j] * bn[j];
            sprob[tid] = d / (sknorm * sbnorm[bk * MN + tid] + 1e-8f);
        }
        __syncthreads();

        // softmax over 128 (warp 0)
        if (warp == 0) {
            float v[4];
#pragma unroll
            for (int q = 0; q < 4; q++) v[q] = sprob[q * 32 + lane];
            float mx = fmaxf(fmaxf(v[0], v[1]), fmaxf(v[2], v[3]));
#pragma unroll
            for (int o = 16; o > 0; o >>= 1)
                mx = fmaxf(mx, __shfl_xor_sync(0xffffffffu, mx, o));
            float e[4], s = 0.f;
#pragma unroll
            for (int q = 0; q < 4; q++) {
                e[q] = expf(v[q] - mx);
                s += e[q];
            }
#pragma unroll
            for (int o = 16; o > 0; o >>= 1)
                s += __shfl_xor_sync(0xffffffffu, s, o);
            float inv = 1.f / s;
#pragma unroll
            for (int q = 0; q < 4; q++) sprob[q * 32 + lane] = e[q] * inv;
        }
        __syncthreads();

        // r = w @ bank  (20 outputs, 128-length dots)
        if (tid < MW) {
            float a = 0.f;
            for (int n = 0; n < MN; n++) a += sprob[n] * sbank[n * MW + tid];
            sr[tid] = a;
        }
        __syncthreads();

        // h_new = relu(pre + r @ W_read + b_read); store to smem + g_H
        {
            const size_t rowoff = ((size_t)b * T_SZ + t) * NH;
            const float4* pre4 = (const float4*)(g_pre + rowoff);
            const float4* br4 = (const float4*)(b_read);
            float4* H4 = (float4*)(g_H + rowoff);
            float4* sh4 = (float4*)sh;
            for (int j4 = tid; j4 < NH / 4; j4 += 256) {
                float4 v = pre4[j4];
                float4 bb = br4[j4];
                v.x += bb.x; v.y += bb.y; v.z += bb.z; v.w += bb.w;
#pragma unroll
                for (int m = 0; m < MW; m++) {
                    float rm = sr[m];
                    float4 w = *(const float4*)(W_read + (size_t)m * NH + j4 * 4);
                    v.x += rm * w.x; v.y += rm * w.y;
                    v.z += rm * w.z; v.w += rm * w.w;
                }
                v.x = fmaxf(v.x, 0.f); v.y = fmaxf(v.y, 0.f);
                v.z = fmaxf(v.z, 0.f); v.w = fmaxf(v.w, 0.f);
                sh4[j4] = v;
                H4[j4] = v;
            }
        }
        __syncthreads();
    }
}

extern "C" void kernel_launch(void* const* d_in, const int* in_sizes, int n_in,
                              void* d_out, int out_size) {
    const float* x      = (const float*)d_in[0];   // [B,T,1,NI] == [4096, 2048]
    const float* h0     = (const float*)d_in[1];   // [B, NH]
    const float* W_in   = (const float*)d_in[2];   // [NI, NH]
    const float* b_in   = (const float*)d_in[3];   // [NH]
    const float* W_read = (const float*)d_in[4];   // [MW, NH]
    const float* b_read = (const float*)d_in[5];   // [NH]
    const float* W_out  = (const float*)d_in[6];   // [NH, NI]
    const float* b_out  = (const float*)d_in[7];   // [NI]
    const float* W_key  = (const float*)d_in[8];   // [NH, MW]
    const float* b_key  = (const float*)d_in[9];   // [MW]
    const float* memory = (const float*)d_in[10];  // [MB, MN, MW]
    float* out = (float*)d_out;                    // [B, T, NI]

    // 1) pre = x @ W_in + b_in  -> g_pre
    gemm_k<0><<<dim3(NH / 128, M_ROWS / 128), 256>>>(x, W_in, b_in, nullptr,
                                                     M_ROWS, NH, NI);
    // 2) sequential recurrence (batch-parallel, one block per batch row) -> g_H
    recur_k<<<B_SZ, 256>>>(h0, W_key, b_key, W_read, b_read, memory);
    // 3) out = clip(g_H @ W_out + b_out, 0, 1)
    gemm_k<1><<<dim3(NI / 128, M_ROWS / 128), 256>>>(nullptr, W_out, b_out, out,
                                                     M_ROWS, NI, NH);
}

// round 4
// speedup vs baseline: 1.9284x; 1.9284x over previous
#include <cuda_runtime.h>
#include <cuda_bf16.h>
#include <math.h>
#include <stdint.h>

#define B_SZ 64
#define T_SZ 64
#define NI 2048
#define NH 2048
#define MBK 4
#define MN 128
#define MW 20
#define M_ROWS 4096
#define KX 6144  // 3 * 2048 (split-GEMM K extension)

// ---------------- device scratch ---------------------------------------------
__device__ float g_pre[(size_t)M_ROWS * NH];          // x@W_in + b_in
__device__ __nv_bfloat16 g_A[(size_t)M_ROWS * KX];    // [Ah|Ah|Al] (x, then H)
__device__ __nv_bfloat16 g_B0[(size_t)NH * KX];       // W_in^T  [Bh|Bl|Bh]
__device__ __nv_bfloat16 g_B1[(size_t)NH * KX];       // W_out^T [Bh|Bl|Bh]

// ---------------- helpers ----------------------------------------------------
__device__ __forceinline__ uint32_t s2u(const void* p) {
    uint32_t r;
    asm("{ .reg .u64 t; cvta.to.shared.u64 t, %1; cvt.u32.u64 %0, t; }"
        : "=r"(r) : "l"(p));
    return r;
}
#define SWZ(x) ((x) ^ (((x) >> 3) & 0x70))
__device__ __forceinline__ void cpa16(uint32_t s, const void* g) {
    asm volatile("cp.async.cg.shared.global [%0], [%1], 16;" :: "r"(s), "l"(g)
                 : "memory");
}
#define CP_COMMIT asm volatile("cp.async.commit_group;" ::: "memory")
__device__ __forceinline__ void cp_wait2() {
    asm volatile("cp.async.wait_group 2;" ::: "memory");
}
__device__ __forceinline__ void cp_wait0() {
    asm volatile("cp.async.wait_group 0;" ::: "memory");
}

__device__ __forceinline__ void ldsm4(uint32_t* r, uint32_t a) {
    asm volatile("ldmatrix.sync.aligned.m8n8.x4.shared.b16 {%0,%1,%2,%3}, [%4];"
                 : "=r"(r[0]), "=r"(r[1]), "=r"(r[2]), "=r"(r[3]) : "r"(a));
}
__device__ __forceinline__ void mma16816(float* c, const uint32_t* a,
                                         const uint32_t* b) {
    asm volatile(
        "mma.sync.aligned.m16n8k16.row.col.f32.bf16.bf16.f32 "
        "{%0,%1,%2,%3}, {%4,%5,%6,%7}, {%8,%9}, {%0,%1,%2,%3};"
        : "+f"(c[0]), "+f"(c[1]), "+f"(c[2]), "+f"(c[3])
        : "r"(a[0]), "r"(a[1]), "r"(a[2]), "r"(a[3]), "r"(b[0]), "r"(b[1]));
}

// ---------------- conversion kernels ----------------------------------------
__global__ void conv_x(const float4* __restrict__ x4,
                       __nv_bfloat16* __restrict__ A) {
    int i = blockIdx.x * 256 + threadIdx.x;
    if (i >= M_ROWS * NI / 4) return;
    int row = i >> 9, c4 = i & 511;
    float4 v = x4[i];
    __nv_bfloat16 hx = __float2bfloat16(v.x), hy = __float2bfloat16(v.y);
    __nv_bfloat16 hz = __float2bfloat16(v.z), hw = __float2bfloat16(v.w);
    __nv_bfloat162 h0 = __halves2bfloat162(hx, hy);
    __nv_bfloat162 h1 = __halves2bfloat162(hz, hw);
    __nv_bfloat162 l0 = __halves2bfloat162(
        __float2bfloat16(v.x - __bfloat162float(hx)),
        __float2bfloat16(v.y - __bfloat162float(hy)));
    __nv_bfloat162 l1 = __halves2bfloat162(
        __float2bfloat16(v.z - __bfloat162float(hz)),
        __float2bfloat16(v.w - __bfloat162float(hw)));
    __nv_bfloat162* p = (__nv_bfloat162*)(A + (size_t)row * KX);
    p[2 * c4] = h0;        p[2 * c4 + 1] = h1;
    p[1024 + 2 * c4] = h0; p[1024 + 2 * c4 + 1] = h1;
    p[2048 + 2 * c4] = l0; p[2048 + 2 * c4 + 1] = l1;
}

// W[K=2048][N=2048] -> T[N][KX] = [hi | lo | hi]
__global__ void trans_split(const float* __restrict__ W,
                            __nv_bfloat16* __restrict__ T) {
    __shared__ float s[32][33];
    int n0 = blockIdx.x * 32, k0 = blockIdx.y * 32;
    int tx = threadIdx.x, ty = threadIdx.y;
#pragma unroll
    for (int i = 0; i < 32; i += 8)
        s[ty + i][tx] = W[(size_t)(k0 + ty + i) * NH + n0 + tx];
    __syncthreads();
#pragma unroll
    for (int i = 0; i < 32; i += 8) {
        float v = s[tx][ty + i];
        __nv_bfloat16 h = __float2bfloat16(v);
        __nv_bfloat16 l = __float2bfloat16(v - __bfloat162float(h));
        size_t o = (size_t)(n0 + ty + i) * KX + k0 + tx;
        T[o] = h;
        T[o + 2048] = l;
        T[o + 4096] = h;
    }
}

// ---------------- mma.sync GEMM: C[4096,2048] = A''[.,6144] @ B''^T ----------
#define BM 128
#define BN 128
#define BK 64
#define STG 3
#define STAGE_B 32768  // A 16K + B 16K
#define NT (KX / BK)   // 96
#define GEMM_SMEM (STG * STAGE_B + 1024)

template <int MODE>  // 0: C=g_pre plain, 1: C=out clamp[0,1]
__global__ void __launch_bounds__(256, 1)
gemm_mma(const __nv_bfloat16* __restrict__ Ag,
         const __nv_bfloat16* __restrict__ Bg,
         const float* __restrict__ bias, float* __restrict__ C) {
    extern __shared__ __align__(1024) char dsm[];
    uint32_t base = (s2u(dsm) + 1023u) & ~1023u;
    const int tid = threadIdx.x, lane = tid & 31, wid = tid >> 5;
    const int bx = blockIdx.x, by = blockIdx.y;
    const int wm = wid & 1, wn = wid >> 1;  // warp grid 2(M) x 4(N)

    const __nv_bfloat16* Abase = Ag + (size_t)(by * BM + (tid >> 3)) * KX +
                                 (tid & 7) * 8;
    const __nv_bfloat16* Bbase = Bg + (size_t)(bx * BN + (tid >> 3)) * KX +
                                 (tid & 7) * 8;

    float acc[4][4][4];
#pragma unroll
    for (int m = 0; m < 4; m++)
#pragma unroll
        for (int n = 0; n < 4; n++)
#pragma unroll
            for (int q = 0; q < 4; q++) acc[m][n][q] = 0.f;

    // per-thread smem store offsets (4 A rows + 4 B rows per stage)
    uint32_t stoff[4];
#pragma unroll
    for (int u = 0; u < 4; u++) {
        int unit = tid + 256 * u;
        stoff[u] = SWZ((uint32_t)((unit >> 3) * 128 + (unit & 7) * 16));
    }

    auto load_stage = [&](int s, int ks) {
        uint32_t sb = base + s * STAGE_B;
#pragma unroll
        for (int u = 0; u < 4; u++)
            cpa16(sb + stoff[u], Abase + (size_t)(32 * u) * KX + ks * BK);
#pragma unroll
        for (int u = 0; u < 4; u++)
            cpa16(sb + 16384 + stoff[u], Bbase + (size_t)(32 * u) * KX + ks * BK);
    };

    load_stage(0, 0);
    CP_COMMIT;
    load_stage(1, 1);
    CP_COMMIT;

    uint32_t aoff[4], boff[2];
#pragma unroll
    for (int mt = 0; mt < 4; mt++)
        aoff[mt] = (uint32_t)((wm * 64 + mt * 16 + (lane & 15)) * 128 +
                              (lane >> 4) * 16);
#pragma unroll
    for (int p = 0; p < 2; p++)
        boff[p] = (uint32_t)((wn * 32 + p * 16 + (lane & 15)) * 128 +
                             (lane >> 4) * 16);

    for (int ks = 0; ks < NT; ks++) {
        if (ks + STG - 1 < NT) {
            load_stage((ks + STG - 1) % STG, ks + STG - 1);
            CP_COMMIT;
            cp_wait2();
        } else {
            cp_wait0();
        }
        __syncthreads();
        const uint32_t sa = base + (ks % STG) * STAGE_B;
        const uint32_t sb = sa + 16384;
#pragma unroll
        for (int k16 = 0; k16 < 4; k16++) {
            uint32_t aF[4][4], bF[4][2];
#pragma unroll
            for (int mt = 0; mt < 4; mt++)
                ldsm4(aF[mt], sa + SWZ(aoff[mt] + k16 * 32));
#pragma unroll
            for (int p = 0; p < 2; p++) {
                uint32_t t[4];
                ldsm4(t, sb + SWZ(boff[p] + k16 * 32));
                bF[2 * p][0] = t[0];
                bF[2 * p][1] = t[2];
                bF[2 * p + 1][0] = t[1];
                bF[2 * p + 1][1] = t[3];
            }
#pragma unroll
            for (int mt = 0; mt < 4; mt++)
#pragma unroll
                for (int nt = 0; nt < 4; nt++)
                    mma16816(acc[mt][nt], aF[mt], bF[nt]);
        }
        __syncthreads();
    }

    // epilogue
    const int g = lane >> 2, t4 = lane & 3;
#pragma unroll
    for (int mt = 0; mt < 4; mt++) {
        const int r0 = by * BM + wm * 64 + mt * 16 + g;
#pragma unroll
        for (int nt = 0; nt < 4; nt++) {
            const int c0 = bx * BN + wn * 32 + nt * 8 + t4 * 2;
            float2 bb = *(const float2*)&bias[c0];
            float v0 = acc[mt][nt][0] + bb.x, v1 = acc[mt][nt][1] + bb.y;
            float v2 = acc[mt][nt][2] + bb.x, v3 = acc[mt][nt][3] + bb.y;
            if (MODE == 1) {
                v0 = fminf(fmaxf(v0, 0.f), 1.f);
                v1 = fminf(fmaxf(v1, 0.f), 1.f);
                v2 = fminf(fmaxf(v2, 0.f), 1.f);
                v3 = fminf(fmaxf(v3, 0.f), 1.f);
            }
            float2 w0 = {v0, v1}, w1 = {v2, v3};
            *(float2*)&C[(size_t)r0 * NH + c0] = w0;
            *(float2*)&C[(size_t)(r0 + 8) * NH + c0] = w1;
        }
    }
}

// ---------------- recurrence: one block/batch row, 512 threads ---------------
#define RS_KEY 0
#define RS_H 43008
#define RS_BN (RS_H + 2048)
#define RS_RED (RS_BN + 512)
#define RS_PROB (RS_RED + 320)
#define RS_KV (RS_PROB + 128)
#define RS_R (RS_KV + 24)
#define RECUR_SMEM ((RS_R + 32) * 4)

__global__ void __launch_bounds__(512, 1)
recur_k(const float* __restrict__ h0, const float* __restrict__ b_key,
        const float* __restrict__ W_read, const float* __restrict__ b_read,
        const float* __restrict__ memory, const float* __restrict__ W_key) {
    extern __shared__ float rs[];
    float* skey = rs + RS_KEY;   // [2048][21]
    float* sh = rs + RS_H;
    float* sbn = rs + RS_BN;
    float* sred = rs + RS_RED;
    float* sprob = rs + RS_PROB;
    float* skv = rs + RS_KV;     // [0..19]=k, [20]=||k||
    float* sr = rs + RS_R;

    const int b = blockIdx.x;
    const int tid = threadIdx.x;
    const int lane = tid & 31, warp = tid >> 5;

    for (int i = tid; i < NH; i += 512) sh[i] = h0[(size_t)b * NH + i];
    for (int r = tid; r < NH; r += 512) {
        const float* kr = W_key + (size_t)r * MW;
#pragma unroll
        for (int j = 0; j < MW; j++) skey[r * 21 + j] = kr[j];
    }
    for (int i = tid; i < MBK * MN; i += 512) {
        float s = 0.f;
        const float* row = memory + (size_t)i * MW;
#pragma unroll
        for (int m = 0; m < MW; m++) s += row[m] * row[m];
        sbn[i] = sqrtf(s);
    }
    __syncthreads();

    for (int t = 0; t < T_SZ; t++) {
        const int bk = t & (MBK - 1);
        const float* bank = memory + (size_t)bk * MN * MW;

        float part[MW];
#pragma unroll
        for (int j = 0; j < MW; j++) part[j] = 0.f;
        for (int r = tid; r < NH; r += 512) {
            float hv = sh[r];
            const float* kr = &skey[r * 21];
#pragma unroll
            for (int j = 0; j < MW; j++) part[j] += hv * kr[j];
        }
#pragma unroll
        for (int j = 0; j < MW; j++) {
#pragma unroll
            for (int o = 16; o > 0; o >>= 1)
                part[j] += __shfl_xor_sync(0xffffffffu, part[j], o);
        }
        if (lane == 0) {
#pragma unroll
            for (int j = 0; j < MW; j++) sred[warp * MW + j] = part[j];
        }
        __syncthreads();
        if (tid < MW) {
            float s = b_key[tid];
#pragma unroll
            for (int w = 0; w < 16; w++) s += sred[w * MW + tid];
            skv[tid] = s;
        }
        __syncthreads();
        if (tid == 0) {
            float s = 0.f;
#pragma unroll
            for (int j = 0; j < MW; j++) s += skv[j] * skv[j];
            skv[20] = sqrtf(s);
        }
        __syncthreads();

        if (tid < MN) {
            const float4* bn = (const float4*)(bank + (size_t)tid * MW);
            float d = 0.f;
#pragma unroll
            for (int q = 0; q < 5; q++) {
                float4 w = __ldg(&bn[q]);
                d += skv[q * 4 + 0] * w.x + skv[q * 4 + 1] * w.y +
                     skv[q * 4 + 2] * w.z + skv[q * 4 + 3] * w.w;
            }
            sprob[tid] = d / (skv[20] * sbn[bk * MN + tid] + 1e-8f);
        }
        __syncthreads();

        if (warp == 0) {
            float v[4];
#pragma unroll
            for (int q = 0; q < 4; q++) v[q] = sprob[q * 32 + lane];
            float mx = fmaxf(fmaxf(v[0], v[1]), fmaxf(v[2], v[3]));
#pragma unroll
            for (int o = 16; o > 0; o >>= 1)
                mx = fmaxf(mx, __shfl_xor_sync(0xffffffffu, mx, o));
            float e[4], s = 0.f;
#pragma unroll
            for (int q = 0; q < 4; q++) {
                e[q] = expf(v[q] - mx);
                s += e[q];
            }
#pragma unroll
            for (int o = 16; o > 0; o >>= 1)
                s += __shfl_xor_sync(0xffffffffu, s, o);
            float inv = 1.f / s;
#pragma unroll
            for (int q = 0; q < 4; q++) sprob[q * 32 + lane] = e[q] * inv;
        }
        __syncthreads();

        if (tid < MW) {
            float a = 0.f;
#pragma unroll 4
            for (int n = 0; n < MN; n++)
                a += sprob[n] * __ldg(bank + (size_t)n * MW + tid);
            sr[tid] = a;
        }
        __syncthreads();

        {
            const size_t prerow = ((size_t)b * T_SZ + t) * NH;
            float4 v = ((const float4*)(g_pre + prerow))[tid];
            float4 bb = ((const float4*)b_read)[tid];
            v.x += bb.x; v.y += bb.y; v.z += bb.z; v.w += bb.w;
#pragma unroll
            for (int m = 0; m < MW; m++) {
                float rm = sr[m];
                float4 w = ((const float4*)W_read)[m * (NH / 4) + tid];
                v.x += rm * w.x; v.y += rm * w.y;
                v.z += rm * w.z; v.w += rm * w.w;
            }
            v.x = fmaxf(v.x, 0.f); v.y = fmaxf(v.y, 0.f);
            v.z = fmaxf(v.z, 0.f); v.w = fmaxf(v.w, 0.f);
            ((float4*)sh)[tid] = v;

            __nv_bfloat16 hx = __float2bfloat16(v.x), hy = __float2bfloat16(v.y);
            __nv_bfloat16 hz = __float2bfloat16(v.z), hw = __float2bfloat16(v.w);
            __nv_bfloat162 h0p = __halves2bfloat162(hx, hy);
            __nv_bfloat162 h1p = __halves2bfloat162(hz, hw);
            __nv_bfloat162 l0p = __halves2bfloat162(
                __float2bfloat16(v.x - __bfloat162float(hx)),
                __float2bfloat16(v.y - __bfloat162float(hy)));
            __nv_bfloat162 l1p = __halves2bfloat162(
                __float2bfloat16(v.z - __bfloat162float(hz)),
                __float2bfloat16(v.w - __bfloat162float(hw)));
            __nv_bfloat162* pa =
                (__nv_bfloat162*)(g_A + ((size_t)b * T_SZ + t) * KX);
            pa[2 * tid] = h0p;        pa[2 * tid + 1] = h1p;
            pa[1024 + 2 * tid] = h0p; pa[1024 + 2 * tid + 1] = h1p;
            pa[2048 + 2 * tid] = l0p; pa[2048 + 2 * tid + 1] = l1p;
        }
        __syncthreads();
    }
}

// ---------------- host -------------------------------------------------------
extern "C" void kernel_launch(void* const* d_in, const int* in_sizes, int n_in,
                              void* d_out, int out_size) {
    const float* x      = (const float*)d_in[0];
    const float* h0     = (const float*)d_in[1];
    const float* W_in   = (const float*)d_in[2];
    const float* b_in   = (const float*)d_in[3];
    const float* W_read = (const float*)d_in[4];
    const float* b_read = (const float*)d_in[5];
    const float* W_out  = (const float*)d_in[6];
    const float* b_out  = (const float*)d_in[7];
    const float* W_key  = (const float*)d_in[8];
    const float* b_key  = (const float*)d_in[9];
    const float* memory = (const float*)d_in[10];
    float* out = (float*)d_out;

    cudaFuncSetAttribute(gemm_mma<0>, cudaFuncAttributeMaxDynamicSharedMemorySize,
                         GEMM_SMEM);
    cudaFuncSetAttribute(gemm_mma<1>, cudaFuncAttributeMaxDynamicSharedMemorySize,
                         GEMM_SMEM);
    cudaFuncSetAttribute(recur_k, cudaFuncAttributeMaxDynamicSharedMemorySize,
                         RECUR_SMEM);

    __nv_bfloat16 *A, *B0, *B1;
    float* pre;
    cudaGetSymbolAddress((void**)&A, g_A);
    cudaGetSymbolAddress((void**)&B0, g_B0);
    cudaGetSymbolAddress((void**)&B1, g_B1);
    cudaGetSymbolAddress((void**)&pre, g_pre);

    conv_x<<<(M_ROWS * NI / 4 + 255) / 256, 256>>>((const float4*)x, A);
    trans_split<<<dim3(64, 64), dim3(32, 8)>>>(W_in, B0);
    trans_split<<<dim3(64, 64), dim3(32, 8)>>>(W_out, B1);

    gemm_mma<0><<<dim3(NH / BN, M_ROWS / BM), 256, GEMM_SMEM>>>(A, B0, b_in, pre);
    recur_k<<<B_SZ, 512, RECUR_SMEM>>>(h0, b_key, W_read, b_read, memory, W_key);
    gemm_mma<1><<<dim3(NI / BN, M_ROWS / BM), 256, GEMM_SMEM>>>(A, B1, b_out, out);
}